// round 5
// baseline (speedup 1.0000x reference)
#include <cuda_runtime.h>
#include <cstdint>

// InversePixelShuffle (pixel_unshuffle, k=2)
// in : (B=8, C=32, H=512, W=512) fp32
// out: (B=8, 128, 256, 256) fp32
// out[b, c*4 + y*2 + x, ho, wo] = in[b, c, 2*ho + y, 2*wo + x]
//
// Persistent grid-stride version of the R2 layout (best measured DRAM%).
// Launch exactly 148*8 CTAs (one full resident wave); each warp strides
// over input rows. This removes the ~13 wave transitions and the per-wave
// tail/spread of the 16384-CTA launch while keeping the identical
// access pattern:
//   warp <-> input row (bc, h). Lane l loads float4 pairs (2l,2l+1) and
//   (64+2l,65+2l); register deinterleave yields one float4 of even-w
//   (channel co = bc*4 + 2y) and one of odd-w (channel co+1) at output
//   row ho = h/2. Stores are lane-contiguous 512B/warp; strided loads'
//   complementary halves merge within the warp so DRAM reads lines once.

static constexpr unsigned H_IN       = 512;
static constexpr unsigned NUM_ROWS   = 8u * 32u * 512u;   // 131072
static constexpr unsigned OUT_CH_F4  = 256u * 256u / 4u;  // 16384
static constexpr unsigned OUT_ROW_F4 = 256u / 4u;         // 64

static constexpr unsigned NUM_SMS      = 148;
static constexpr unsigned CTAS_PER_SM  = 8;
static constexpr unsigned THREADS      = 256;             // 8 warps/CTA
static constexpr unsigned TOTAL_WARPS  = NUM_SMS * CTAS_PER_SM * (THREADS / 32);  // 9472

__global__ void __launch_bounds__(THREADS)
inverse_pixel_shuffle_kernel(const float4* __restrict__ in,
                             float4* __restrict__ out) {
    unsigned tid   = blockIdx.x * blockDim.x + threadIdx.x;
    unsigned lane  = tid & 31u;
    unsigned warp0 = tid >> 5;
    unsigned l2    = 2u * lane;

    for (unsigned wid = warp0; wid < NUM_ROWS; wid += TOTAL_WARPS) {
        unsigned h  = wid & (H_IN - 1);
        unsigned bc = wid >> 9;                        // b*32 + c

        const float4* inrow = in + ((size_t)wid << 7); // wid * 128 float4

        // Four independent loads, front-batched.
        float4 a0 = inrow[l2];
        float4 a1 = inrow[l2 + 1u];
        float4 b0 = inrow[64u + l2];
        float4 b1 = inrow[64u + l2 + 1u];

        unsigned ho = h >> 1;
        unsigned y  = h & 1u;
        unsigned co = bc * 4u + y * 2u;                // b*128 + c*4 + 2y

        float4* orow = out + ((size_t)co * 256u + ho) * OUT_ROW_F4;

        // Even-w -> channel co ; odd-w -> channel co+1.
        orow[lane]                    = make_float4(a0.x, a0.z, a1.x, a1.z);
        orow[32u + lane]              = make_float4(b0.x, b0.z, b1.x, b1.z);
        orow[OUT_CH_F4 + lane]        = make_float4(a0.y, a0.w, a1.y, a1.w);
        orow[OUT_CH_F4 + 32u + lane]  = make_float4(b0.y, b0.w, b1.y, b1.w);
    }
}

extern "C" void kernel_launch(void* const* d_in, const int* in_sizes, int n_in,
                              void* d_out, int out_size) {
    const float4* in  = (const float4*)d_in[0];
    float4*       out = (float4*)d_out;

    inverse_pixel_shuffle_kernel<<<NUM_SMS * CTAS_PER_SM, THREADS>>>(in, out);
}

// round 6
// speedup vs baseline: 1.1266x; 1.1266x over previous
#include <cuda_runtime.h>
#include <cstdint>

// InversePixelShuffle (pixel_unshuffle, k=2)
// in : (B=8, C=32, H=512, W=512) fp32
// out: (B=8, 128, 256, 256) fp32
// out[b, c*4 + y*2 + x, ho, wo] = in[b, c, 2*ho + y, 2*wo + x]
//
// Fully-dense variant: warp <-> input row. Lane l loads row[32k + l],
// k=0..3 — four 512B perfectly contiguous LDG.128 wavefronts (no strided
// half-sector accesses, no MSHR-merge reliance). Deinterleave via
// shfl_xor(1): lane pair (2m, 2m+1) holds row float4s 2m, 2m+1; the even
// lane assembles the even-w output float4 (own x,z + partner x,z), the
// odd lane the odd-w one (partner y,w + own y,w). Each STG then writes
// two dense 256B segments (even lanes -> channel co, odd -> co+1), all
// sectors full.

static constexpr unsigned H_IN       = 512;
static constexpr unsigned NUM_ROWS   = 8u * 32u * 512u;   // 131072 warps
static constexpr unsigned OUT_CH_F4  = 256u * 256u / 4u;  // 16384
static constexpr unsigned OUT_ROW_F4 = 256u / 4u;         // 64

__device__ __forceinline__ float4 deinterleave(float4 v, unsigned odd) {
    // Exchange with partner lane (lane ^ 1):
    // even lane sends (y,w) [partner needs them], odd lane sends (x,z).
    float sa = odd ? v.x : v.y;
    float sb = odd ? v.z : v.w;
    float ra = __shfl_xor_sync(0xFFFFFFFFu, sa, 1);
    float rb = __shfl_xor_sync(0xFFFFFFFFu, sb, 1);
    // even lane: (x, z, partner.x, partner.z)  -> even-w float4
    // odd  lane: (partner.y, partner.w, y, w)  -> odd-w  float4
    return odd ? make_float4(ra, rb, v.y, v.w)
               : make_float4(v.x, v.z, ra, rb);
}

__global__ void __launch_bounds__(256)
inverse_pixel_shuffle_kernel(const float4* __restrict__ in,
                             float4* __restrict__ out) {
    unsigned tid  = blockIdx.x * blockDim.x + threadIdx.x;
    unsigned lane = tid & 31u;
    unsigned wid  = tid >> 5;                  // one warp per input row

    unsigned h  = wid & (H_IN - 1);
    unsigned bc = wid >> 9;                    // b*32 + c

    const float4* inrow = in + ((size_t)wid << 7);   // wid * 128 float4

    // Four dense, front-batched loads (512B contiguous per instruction).
    float4 v0 = inrow[lane];
    float4 v1 = inrow[32u + lane];
    float4 v2 = inrow[64u + lane];
    float4 v3 = inrow[96u + lane];

    unsigned odd = lane & 1u;

    float4 o0 = deinterleave(v0, odd);
    float4 o1 = deinterleave(v1, odd);
    float4 o2 = deinterleave(v2, odd);
    float4 o3 = deinterleave(v3, odd);

    unsigned ho = h >> 1;
    unsigned y  = h & 1u;
    unsigned co = bc * 4u + y * 2u;            // b*128 + c*4 + 2y

    // Even lanes write channel co, odd lanes channel co+1, at float4
    // index 16k + lane/2 within the output row.
    float4* orow = out + ((size_t)co * 256u + ho) * OUT_ROW_F4
                 + (odd ? OUT_CH_F4 : 0u) + (lane >> 1);

    orow[0]   = o0;
    orow[16]  = o1;
    orow[32]  = o2;
    orow[48]  = o3;
}

extern "C" void kernel_launch(void* const* d_in, const int* in_sizes, int n_in,
                              void* d_out, int out_size) {
    const float4* in  = (const float4*)d_in[0];
    float4*       out = (float4*)d_out;

    const unsigned threads = 256;                         // 8 warps = 8 rows/block
    const unsigned blocks  = (NUM_ROWS * 32u) / threads;  // 16384
    inverse_pixel_shuffle_kernel<<<blocks, threads>>>(in, out);
}

// round 7
// speedup vs baseline: 1.1288x; 1.0020x over previous
#include <cuda_runtime.h>
#include <cstdint>

// InversePixelShuffle (pixel_unshuffle, k=2)
// in : (B=8, C=32, H=512, W=512) fp32
// out: (B=8, 128, 256, 256) fp32
// out[b, c*4 + y*2 + x, ho, wo] = in[b, c, 2*ho + y, 2*wo + x]
//
// 256-bit (v8.f32, sm_100+) variant: warp <-> input row. Lane l owns
// input float4s 4l..4l+3 (64 bytes) loaded as two LDG.256. The 16 floats
// deinterleave in registers into 8 even-w floats (output float4s 2l,2l+1
// of channel co) and 8 odd-w floats (same indices of channel co+1), each
// written with one STG.256. Every transaction is fully dense and 32B
// aligned; per-instruction warp footprint is 1024B on both sides.

static constexpr unsigned H_IN       = 512;
static constexpr unsigned NUM_ROWS   = 8u * 32u * 512u;   // 131072 warps
static constexpr unsigned OUT_CH_F4  = 256u * 256u / 4u;  // 16384
static constexpr unsigned OUT_ROW_F4 = 256u / 4u;         // 64

__device__ __forceinline__ void ldg256(const float4* p, float4& a, float4& b) {
    asm volatile("ld.global.v8.f32 {%0,%1,%2,%3,%4,%5,%6,%7}, [%8];"
                 : "=f"(a.x), "=f"(a.y), "=f"(a.z), "=f"(a.w),
                   "=f"(b.x), "=f"(b.y), "=f"(b.z), "=f"(b.w)
                 : "l"(p));
}

__device__ __forceinline__ void stg256(float4* p, float4 a, float4 b) {
    asm volatile("st.global.v8.f32 [%0], {%1,%2,%3,%4,%5,%6,%7,%8};"
                 :: "l"(p),
                    "f"(a.x), "f"(a.y), "f"(a.z), "f"(a.w),
                    "f"(b.x), "f"(b.y), "f"(b.z), "f"(b.w)
                 : "memory");
}

__global__ void __launch_bounds__(256)
inverse_pixel_shuffle_kernel(const float4* __restrict__ in,
                             float4* __restrict__ out) {
    unsigned tid  = blockIdx.x * blockDim.x + threadIdx.x;
    unsigned lane = tid & 31u;
    unsigned wid  = tid >> 5;                 // one warp per input row

    unsigned h  = wid & (H_IN - 1);
    unsigned bc = wid >> 9;                   // b*32 + c

    const float4* inrow = in + ((size_t)wid << 7);   // wid * 128 float4
    unsigned l4 = 4u * lane;

    // Two 256-bit loads: input float4s 4l..4l+1 and 4l+2..4l+3.
    float4 a0, a1, b0, b1;
    ldg256(inrow + l4,      a0, a1);
    ldg256(inrow + l4 + 2u, b0, b1);

    unsigned ho = h >> 1;
    unsigned y  = h & 1u;
    unsigned co = bc * 4u + y * 2u;           // b*128 + c*4 + 2y

    float4* orow = out + ((size_t)co * 256u + ho) * OUT_ROW_F4 + 2u * lane;

    // Even-w floats of the 16-float chunk -> channel co (one 256-bit store).
    stg256(orow,
           make_float4(a0.x, a0.z, a1.x, a1.z),
           make_float4(b0.x, b0.z, b1.x, b1.z));
    // Odd-w floats -> channel co+1.
    stg256(orow + OUT_CH_F4,
           make_float4(a0.y, a0.w, a1.y, a1.w),
           make_float4(b0.y, b0.w, b1.y, b1.w));
}

extern "C" void kernel_launch(void* const* d_in, const int* in_sizes, int n_in,
                              void* d_out, int out_size) {
    const float4* in  = (const float4*)d_in[0];
    float4*       out = (float4*)d_out;

    const unsigned threads = 256;                         // 8 warps = 8 rows/block
    const unsigned blocks  = (NUM_ROWS * 32u) / threads;  // 16384
    inverse_pixel_shuffle_kernel<<<blocks, threads>>>(in, out);
}